// round 1
// baseline (speedup 1.0000x reference)
#include <cuda_runtime.h>
#include <cuda_bf16.h>

// Problem constants
#define B_ 8
#define F_ 128
#define M_ 256
#define N_ 1024
#define H_ 64
#define O_ 128

// ---------------- scratch (device globals; no allocations allowed) ----------
__device__ float d_cos[B_ * N_ * M_];     // cos stored [b][n][m] (8 MB)
__device__ float d_Ap [B_ * H_ * M_];     // BN1-folded W1[:,1:]@t  [b][h][m]
__device__ float d_nt [B_ * M_];
__device__ float d_ns [B_ * N_];
__device__ float d_w0 [H_];               // alpha1 * W1[:,0]
__device__ float d_b2v[H_], d_b3v[H_], d_bc1v[H_];
__device__ float d_W2d[H_ * H_ * 2];      // [k][g] duplicated pairs (alpha2*W2[g][k])
__device__ float d_W3d[H_ * H_ * 2];
__device__ float d_Wc1t[H_ * H_];         // [h][g] = alphac1*Wc1[g][h]
__device__ float d_Wc2t[H_ * O_];         // [h][o] = Wc2[o][h]
__device__ float d_p  [B_ * N_ * H_];     // pooled features [b][n][h] (2 MB)

typedef unsigned long long ull;

__device__ __forceinline__ ull ffma2(ull a, ull b, ull c) {
    ull d;
    asm("fma.rn.f32x2 %0, %1, %2, %3;" : "=l"(d) : "l"(a), "l"(b), "l"(c));
    return d;
}
__device__ __forceinline__ float ull_lo(ull u) { return __uint_as_float((unsigned)u); }
__device__ __forceinline__ float ull_hi(ull u) { return __uint_as_float((unsigned)(u >> 32)); }

// ---------------- K0: fold BN into weights ----------------------------------
__global__ void fold_kernel(const float* __restrict__ W1, const float* __restrict__ W2,
                            const float* __restrict__ W3, const float* __restrict__ Wc1,
                            const float* __restrict__ Wc2,
                            const float* __restrict__ g1, const float* __restrict__ v1,
                            const float* __restrict__ g2, const float* __restrict__ b2,
                            const float* __restrict__ m2, const float* __restrict__ v2,
                            const float* __restrict__ g3, const float* __restrict__ b3,
                            const float* __restrict__ m3, const float* __restrict__ v3,
                            const float* __restrict__ gc1, const float* __restrict__ bc1,
                            const float* __restrict__ mc1, const float* __restrict__ vc1) {
    __shared__ float a2s[H_], a3s[H_], ac1s[H_];
    int tid = threadIdx.x;
    if (tid < H_) {
        float A1 = g1[tid] * rsqrtf(v1[tid] + 1e-5f);
        d_w0[tid] = A1 * W1[tid * (F_ + 1)];
        float A2 = g2[tid] * rsqrtf(v2[tid] + 1e-5f);
        a2s[tid] = A2;  d_b2v[tid] = b2[tid] - A2 * m2[tid];
        float A3 = g3[tid] * rsqrtf(v3[tid] + 1e-5f);
        a3s[tid] = A3;  d_b3v[tid] = b3[tid] - A3 * m3[tid];
        float Ac = gc1[tid] * rsqrtf(vc1[tid] + 1e-5f);
        ac1s[tid] = Ac; d_bc1v[tid] = bc1[tid] - Ac * mc1[tid];
    }
    __syncthreads();
    for (int i = tid; i < H_ * H_; i += 256) {
        int k = i >> 6, g = i & 63;
        float w2v = a2s[g] * W2[g * H_ + k];
        d_W2d[k * 128 + 2 * g] = w2v; d_W2d[k * 128 + 2 * g + 1] = w2v;
        float w3v = a3s[g] * W3[g * H_ + k];
        d_W3d[k * 128 + 2 * g] = w3v; d_W3d[k * 128 + 2 * g + 1] = w3v;
        d_Wc1t[k * H_ + g] = ac1s[g] * Wc1[g * H_ + k];
    }
    for (int i = tid; i < H_ * O_; i += 256) {
        int h = i >> 7, o = i & 127;
        d_Wc2t[h * O_ + o] = Wc2[o * H_ + h];
    }
}

// ---------------- K1: A' = BN1-folded W1[:,1:] @ t ---------------------------
__global__ void ap_kernel(const float* __restrict__ t, const float* __restrict__ W1,
                          const float* __restrict__ g1, const float* __restrict__ b1,
                          const float* __restrict__ m1, const float* __restrict__ v1) {
    int bh = blockIdx.x;            // b*64 + h
    int b = bh >> 6, h = bh & 63;
    int m = threadIdx.x;            // 256 threads
    __shared__ float w[F_];
    if (m < F_) w[m] = W1[h * (F_ + 1) + 1 + m];
    __syncthreads();
    const float* tp = t + (size_t)b * F_ * M_ + m;
    float acc = 0.f;
#pragma unroll 8
    for (int f = 0; f < F_; f++) acc = fmaf(w[f], tp[f * M_], acc);
    float A1 = g1[h] * rsqrtf(v1[h] + 1e-5f);
    float B1 = b1[h] - A1 * m1[h];
    d_Ap[bh * M_ + m] = fmaf(A1, acc, B1);
}

// ---------------- K2: column norms ------------------------------------------
__global__ void norm_kernel(const float* __restrict__ t, const float* __restrict__ s) {
    int idx = blockIdx.x * 256 + threadIdx.x;  // B*(M+N) = 10240
    int b = idx / (M_ + N_);
    int r = idx - b * (M_ + N_);
    float acc = 0.f;
    if (r < M_) {
        const float* p = t + (size_t)b * F_ * M_ + r;
#pragma unroll 8
        for (int f = 0; f < F_; f++) { float v = p[f * M_]; acc = fmaf(v, v, acc); }
        d_nt[b * M_ + r] = sqrtf(acc);
    } else {
        int n = r - M_;
        const float* p = s + (size_t)b * F_ * N_ + n;
#pragma unroll 8
        for (int f = 0; f < F_; f++) { float v = p[f * N_]; acc = fmaf(v, v, acc); }
        d_ns[b * N_ + n] = sqrtf(acc);
    }
}

// ---------------- K3: cosine-similarity GEMM, stores [b][n][m] ---------------
__global__ void __launch_bounds__(256) cos_kernel(const float* __restrict__ t,
                                                  const float* __restrict__ s) {
    int b = blockIdx.z;
    int m0 = blockIdx.y * 64;
    int n0 = blockIdx.x * 64;
    __shared__ float ts[16][64];
    __shared__ float ss[16][64];
    int tid = threadIdx.x, ty = tid >> 4, tx = tid & 15;
    float acc[4][4] = {};
    const float* tb = t + (size_t)b * F_ * M_;
    const float* sb = s + (size_t)b * F_ * N_;
    for (int f0 = 0; f0 < F_; f0 += 16) {
        __syncthreads();
#pragma unroll
        for (int i = 0; i < 4; i++) {
            int e = tid + i * 256;
            int fr = e >> 6, cc = e & 63;
            ts[fr][cc] = tb[(f0 + fr) * M_ + m0 + cc];
            ss[fr][cc] = sb[(f0 + fr) * N_ + n0 + cc];
        }
        __syncthreads();
#pragma unroll
        for (int k = 0; k < 16; k++) {
            float4 av = *(const float4*)&ts[k][4 * ty];
            float4 bv = *(const float4*)&ss[k][4 * tx];
            float a0 = av.x, a1 = av.y, a2 = av.z, a3 = av.w;
            float b0 = bv.x, b1 = bv.y, b2 = bv.z, b3 = bv.w;
            acc[0][0] = fmaf(a0, b0, acc[0][0]); acc[0][1] = fmaf(a0, b1, acc[0][1]);
            acc[0][2] = fmaf(a0, b2, acc[0][2]); acc[0][3] = fmaf(a0, b3, acc[0][3]);
            acc[1][0] = fmaf(a1, b0, acc[1][0]); acc[1][1] = fmaf(a1, b1, acc[1][1]);
            acc[1][2] = fmaf(a1, b2, acc[1][2]); acc[1][3] = fmaf(a1, b3, acc[1][3]);
            acc[2][0] = fmaf(a2, b0, acc[2][0]); acc[2][1] = fmaf(a2, b1, acc[2][1]);
            acc[2][2] = fmaf(a2, b2, acc[2][2]); acc[2][3] = fmaf(a2, b3, acc[2][3]);
            acc[3][0] = fmaf(a3, b0, acc[3][0]); acc[3][1] = fmaf(a3, b1, acc[3][1]);
            acc[3][2] = fmaf(a3, b2, acc[3][2]); acc[3][3] = fmaf(a3, b3, acc[3][3]);
        }
    }
    float ntv[4], nsv[4];
#pragma unroll
    for (int r = 0; r < 4; r++) ntv[r] = d_nt[b * M_ + m0 + 4 * ty + r];
#pragma unroll
    for (int c = 0; c < 4; c++) nsv[c] = d_ns[b * N_ + n0 + 4 * tx + c];
#pragma unroll
    for (int c = 0; c < 4; c++) {
        int n = n0 + 4 * tx + c;
        float4 v;
        v.x = acc[0][c] / fmaxf(ntv[0] * nsv[c], 1e-8f);
        v.y = acc[1][c] / fmaxf(ntv[1] * nsv[c], 1e-8f);
        v.z = acc[2][c] / fmaxf(ntv[2] * nsv[c], 1e-8f);
        v.w = acc[3][c] / fmaxf(ntv[3] * nsv[c], 1e-8f);
        *(float4*)&d_cos[((size_t)b * N_ + n) * M_ + m0 + 4 * ty] = v;
    }
}

// ---------------- K4: fused MLP + maxpool, one block per (b,n) --------------
// smem floats: w2s 8192 | w3s 8192 | h1s 4096 | h2s 4096 | cosv 256 |
//              w0s 64 | b2s 64 | b3s 64 | red 1024  => 26048 floats = 104192 B
#define MAIN_SMEM_FLOATS 26048
__global__ void __launch_bounds__(256) main_kernel() {
    extern __shared__ float smf[];
    float* w2s  = smf;
    float* w3s  = smf + 8192;
    float* h1s  = smf + 16384;
    float* h2s  = smf + 20480;
    float* cosv = smf + 24576;
    float* w0s  = smf + 24832;
    float* b2s  = smf + 24896;
    float* b3s  = smf + 24960;
    float* red  = smf + 25024;

    int n = blockIdx.x, b = blockIdx.y;
    int tid = threadIdx.x, ty = tid >> 4, tx = tid & 15;

    {
        const float4* src2 = (const float4*)d_W2d;
        const float4* src3 = (const float4*)d_W3d;
        float4* dst2 = (float4*)w2s;
        float4* dst3 = (float4*)w3s;
#pragma unroll
        for (int i = 0; i < 8; i++) {
            dst2[tid + i * 256] = src2[tid + i * 256];
            dst3[tid + i * 256] = src3[tid + i * 256];
        }
        if (tid < 64)
            ((float4*)cosv)[tid] = ((const float4*)(d_cos + ((size_t)b * N_ + n) * M_))[tid];
        else if (tid < 128) w0s[tid - 64]  = d_w0[tid - 64];
        else if (tid < 192) b2s[tid - 128] = d_b2v[tid - 128];
        else                b3s[tid - 192] = d_b3v[tid - 192];
    }

    float pmax[4] = {0.f, 0.f, 0.f, 0.f};
    const float* ApB = d_Ap + (size_t)b * H_ * M_;

    for (int chunk = 0; chunk < 4; chunk++) {
        int m0 = chunk * 64;
        __syncthreads();
        // build H1 = relu(A' + w0' * cos)
#pragma unroll
        for (int i = 0; i < 16; i++) {
            int idx = tid + i * 256;
            int hh = idx >> 6, mm = idx & 63;
            float c = cosv[m0 + mm];
            float a = __ldg(ApB + hh * M_ + m0 + mm);
            h1s[idx] = fmaxf(fmaf(w0s[hh], c, a), 0.f);
        }
        __syncthreads();

        // GEMM1: H2 = relu(W2f @ H1 + b2)
        {
            ull acc[4][2] = {};
#pragma unroll 16
            for (int k = 0; k < 64; k++) {
                ulonglong2 a01 = *(const ulonglong2*)(w2s + k * 128 + 8 * ty);
                ulonglong2 a23 = *(const ulonglong2*)(w2s + k * 128 + 8 * ty + 4);
                ulonglong2 bb  = *(const ulonglong2*)(h1s + k * 64 + 4 * tx);
                acc[0][0] = ffma2(a01.x, bb.x, acc[0][0]); acc[0][1] = ffma2(a01.x, bb.y, acc[0][1]);
                acc[1][0] = ffma2(a01.y, bb.x, acc[1][0]); acc[1][1] = ffma2(a01.y, bb.y, acc[1][1]);
                acc[2][0] = ffma2(a23.x, bb.x, acc[2][0]); acc[2][1] = ffma2(a23.x, bb.y, acc[2][1]);
                acc[3][0] = ffma2(a23.y, bb.x, acc[3][0]); acc[3][1] = ffma2(a23.y, bb.y, acc[3][1]);
            }
#pragma unroll
            for (int r = 0; r < 4; r++) {
                float bb2 = b2s[4 * ty + r];
                float4 v;
                v.x = fmaxf(ull_lo(acc[r][0]) + bb2, 0.f);
                v.y = fmaxf(ull_hi(acc[r][0]) + bb2, 0.f);
                v.z = fmaxf(ull_lo(acc[r][1]) + bb2, 0.f);
                v.w = fmaxf(ull_hi(acc[r][1]) + bb2, 0.f);
                *(float4*)(h2s + (4 * ty + r) * 64 + 4 * tx) = v;
            }
        }
        __syncthreads();

        // GEMM2: H3 = relu(W3f @ H2 + b3); fold max over m into pmax
        {
            ull acc[4][2] = {};
#pragma unroll 16
            for (int k = 0; k < 64; k++) {
                ulonglong2 a01 = *(const ulonglong2*)(w3s + k * 128 + 8 * ty);
                ulonglong2 a23 = *(const ulonglong2*)(w3s + k * 128 + 8 * ty + 4);
                ulonglong2 bb  = *(const ulonglong2*)(h2s + k * 64 + 4 * tx);
                acc[0][0] = ffma2(a01.x, bb.x, acc[0][0]); acc[0][1] = ffma2(a01.x, bb.y, acc[0][1]);
                acc[1][0] = ffma2(a01.y, bb.x, acc[1][0]); acc[1][1] = ffma2(a01.y, bb.y, acc[1][1]);
                acc[2][0] = ffma2(a23.x, bb.x, acc[2][0]); acc[2][1] = ffma2(a23.x, bb.y, acc[2][1]);
                acc[3][0] = ffma2(a23.y, bb.x, acc[3][0]); acc[3][1] = ffma2(a23.y, bb.y, acc[3][1]);
            }
#pragma unroll
            for (int r = 0; r < 4; r++) {
                float bb3 = b3s[4 * ty + r];
                float x0 = ull_lo(acc[r][0]) + bb3;
                float x1 = ull_hi(acc[r][0]) + bb3;
                float x2 = ull_lo(acc[r][1]) + bb3;
                float x3 = ull_hi(acc[r][1]) + bb3;
                // pmax >= 0 already, so relu is implied by the running max
                pmax[r] = fmaxf(pmax[r], fmaxf(fmaxf(x0, x1), fmaxf(x2, x3)));
            }
        }
    }

    __syncthreads();
#pragma unroll
    for (int r = 0; r < 4; r++) red[(4 * ty + r) * 16 + tx] = pmax[r];
    __syncthreads();
    if (tid < 64) {
        float mx = red[tid * 16];
#pragma unroll
        for (int i = 1; i < 16; i++) mx = fmaxf(mx, red[tid * 16 + i]);
        d_p[((size_t)b * N_ + n) * H_ + tid] = mx;
    }
}

// ---------------- K5: head (Wc1 -> relu -> Wc2 + bc2) ------------------------
// smem floats: wc1s 4096 | wc2s 8192 | ps 4096 | cs 64*65=4160 | bc1s 64 => 20608 (82432 B)
#define HEAD_SMEM_FLOATS 20608
__global__ void __launch_bounds__(256) head_kernel(const float* __restrict__ bc2,
                                                   float* __restrict__ out) {
    extern __shared__ float smf[];
    float* wc1s = smf;           // [h][g]
    float* wc2s = smf + 4096;    // [h][o]
    float* ps   = smf + 12288;   // [n][h]
    float* cs   = smf + 16384;   // [n][65]
    float* bc1s = smf + 20544;

    int b = blockIdx.y, n0 = blockIdx.x * 64;
    int tid = threadIdx.x;
#pragma unroll
    for (int i = 0; i < 16; i++) {
        int idx = tid + i * 256;
        wc1s[idx] = d_Wc1t[idx];
        ps[idx]   = d_p[((size_t)b * N_ + n0) * H_ + idx];
    }
#pragma unroll
    for (int i = 0; i < 32; i++) {
        int idx = tid + i * 256;
        wc2s[idx] = d_Wc2t[idx];
    }
    if (tid < 64) bc1s[tid] = d_bc1v[tid];
    __syncthreads();

    // c = relu(Wc1f @ p + bc1f)
#pragma unroll
    for (int i = 0; i < 16; i++) {
        int idx = tid + i * 256;
        int nn = idx >> 6, g = idx & 63;
        float acc = bc1s[g];
#pragma unroll 16
        for (int h = 0; h < 64; h++) acc = fmaf(wc1s[h * 64 + g], ps[nn * 64 + h], acc);
        cs[nn * 65 + g] = fmaxf(acc, 0.f);
    }
    __syncthreads();

    // out = Wc2 @ c + bc2
#pragma unroll
    for (int i = 0; i < 32; i++) {
        int idx = tid + i * 256;
        int o = idx >> 6, nn = idx & 63;
        float acc = __ldg(bc2 + o);
#pragma unroll 16
        for (int h = 0; h < 64; h++) acc = fmaf(wc2s[h * 128 + o], cs[nn * 65 + h], acc);
        out[((size_t)b * O_ + o) * N_ + n0 + nn] = acc;
    }
}

// ---------------- launch ------------------------------------------------------
extern "C" void kernel_launch(void* const* d_in, const int* in_sizes, int n_in,
                              void* d_out, int out_size) {
    const float* t   = (const float*)d_in[0];
    const float* s   = (const float*)d_in[1];
    const float* W1  = (const float*)d_in[2];
    const float* W2  = (const float*)d_in[3];
    const float* W3  = (const float*)d_in[4];
    const float* Wc1 = (const float*)d_in[5];
    const float* Wc2 = (const float*)d_in[6];
    const float* bc2 = (const float*)d_in[7];
    const float* g1 = (const float*)d_in[8],  *b1 = (const float*)d_in[9];
    const float* m1 = (const float*)d_in[10], *v1 = (const float*)d_in[11];
    const float* g2 = (const float*)d_in[12], *b2 = (const float*)d_in[13];
    const float* m2 = (const float*)d_in[14], *v2 = (const float*)d_in[15];
    const float* g3 = (const float*)d_in[16], *b3 = (const float*)d_in[17];
    const float* m3 = (const float*)d_in[18], *v3 = (const float*)d_in[19];
    const float* gc1 = (const float*)d_in[20], *bc1 = (const float*)d_in[21];
    const float* mc1 = (const float*)d_in[22], *vc1 = (const float*)d_in[23];
    float* out = (float*)d_out;

    cudaFuncSetAttribute(main_kernel, cudaFuncAttributeMaxDynamicSharedMemorySize,
                         MAIN_SMEM_FLOATS * 4);
    cudaFuncSetAttribute(head_kernel, cudaFuncAttributeMaxDynamicSharedMemorySize,
                         HEAD_SMEM_FLOATS * 4);

    fold_kernel<<<1, 256>>>(W1, W2, W3, Wc1, Wc2, g1, v1,
                            g2, b2, m2, v2, g3, b3, m3, v3, gc1, bc1, mc1, vc1);
    ap_kernel<<<B_ * H_, 256>>>(t, W1, g1, b1, m1, v1);
    norm_kernel<<<(B_ * (M_ + N_)) / 256, 256>>>(t, s);
    cos_kernel<<<dim3(N_ / 64, M_ / 64, B_), 256>>>(t, s);
    main_kernel<<<dim3(N_, B_), 256, MAIN_SMEM_FLOATS * 4>>>();
    head_kernel<<<dim3(N_ / 64, B_), 256, HEAD_SMEM_FLOATS * 4>>>(bc2, out);
}

// round 3
// speedup vs baseline: 2.0597x; 2.0597x over previous
#include <cuda_runtime.h>
#include <cuda_bf16.h>
#include <cstdint>

#define B_ 8
#define F_ 128
#define M_ 256
#define N_ 1024
#define H_ 64
#define O_ 128
#define NPB 4
#define ROWB 400   // Xs bytes per m-row (192 bf16 + 16B pad, 25 x 16B chunks)

// ---------------- scratch (device globals; no allocations allowed) ----------
__device__ __align__(16) float d_cos[B_ * N_ * M_];   // [b][n][m]
__device__ __align__(16) float d_Ap [B_ * H_ * M_];   // [b][h][m]
__device__ float d_nt [B_ * M_];
__device__ float d_ns [B_ * N_];
__device__ float d_w0 [H_];
__device__ float d_b2v[H_], d_b3v[H_], d_bc1v[H_];
// ldmatrix-ready bf16 weight images: [k=192 rows][64 g], 128B rows, 16B-chunk XOR swizzle
__device__ __align__(16) unsigned short d_W2img[192 * 64];
__device__ __align__(16) unsigned short d_W3img[192 * 64];
__device__ __align__(16) float d_Wc1t[H_ * H_];
__device__ __align__(16) float d_Wc2t[H_ * O_];
__device__ __align__(16) float d_p  [B_ * N_ * H_];

// ================= tensor-core helpers (sm_80-era PTX, valid on sm_103) =====
__device__ __forceinline__ uint32_t smem_to_u32(const void* p) {
    uint32_t a;
    asm("{ .reg .u64 t; cvta.to.shared.u64 t, %1; cvt.u32.u64 %0, t; }" : "=r"(a) : "l"(p));
    return a;
}
__device__ __forceinline__ void ldsm_x4(uint32_t r[4], uint32_t addr) {
    asm volatile("ldmatrix.sync.aligned.m8n8.x4.shared.b16 {%0,%1,%2,%3}, [%4];"
                 : "=r"(r[0]), "=r"(r[1]), "=r"(r[2]), "=r"(r[3]) : "r"(addr));
}
__device__ __forceinline__ void ldsm_x4t(uint32_t r[4], uint32_t addr) {
    asm volatile("ldmatrix.sync.aligned.m8n8.x4.trans.shared.b16 {%0,%1,%2,%3}, [%4];"
                 : "=r"(r[0]), "=r"(r[1]), "=r"(r[2]), "=r"(r[3]) : "r"(addr));
}
__device__ __forceinline__ void mma16816(float d[4], const uint32_t a[4],
                                         uint32_t b0, uint32_t b1) {
    asm volatile("mma.sync.aligned.m16n8k16.row.col.f32.bf16.bf16.f32 "
                 "{%0,%1,%2,%3}, {%4,%5,%6,%7}, {%8,%9}, {%0,%1,%2,%3};"
                 : "+f"(d[0]), "+f"(d[1]), "+f"(d[2]), "+f"(d[3])
                 : "r"(a[0]), "r"(a[1]), "r"(a[2]), "r"(a[3]), "r"(b0), "r"(b1));
}
__device__ __forceinline__ uint32_t pack_split(float y0, float y1, uint32_t& lo) {
    __nv_bfloat16 h0 = __float2bfloat16(y0), h1 = __float2bfloat16(y1);
    __nv_bfloat16 l0 = __float2bfloat16(y0 - __bfloat162float(h0));
    __nv_bfloat16 l1 = __float2bfloat16(y1 - __bfloat162float(h1));
    lo = (uint32_t)__bfloat16_as_ushort(l0) | ((uint32_t)__bfloat16_as_ushort(l1) << 16);
    return (uint32_t)__bfloat16_as_ushort(h0) | ((uint32_t)__bfloat16_as_ushort(h1) << 16);
}

// ---------------- K0: fold BN into weights, emit ldmatrix bf16 images --------
__global__ void fold_kernel(const float* __restrict__ W1, const float* __restrict__ W2,
                            const float* __restrict__ W3, const float* __restrict__ Wc1,
                            const float* __restrict__ Wc2,
                            const float* __restrict__ g1, const float* __restrict__ v1,
                            const float* __restrict__ g2, const float* __restrict__ b2,
                            const float* __restrict__ m2, const float* __restrict__ v2,
                            const float* __restrict__ g3, const float* __restrict__ b3,
                            const float* __restrict__ m3, const float* __restrict__ v3,
                            const float* __restrict__ gc1, const float* __restrict__ bc1,
                            const float* __restrict__ mc1, const float* __restrict__ vc1) {
    __shared__ float a2s[H_], a3s[H_], ac1s[H_];
    int tid = threadIdx.x;
    if (tid < H_) {
        float A1 = g1[tid] * rsqrtf(v1[tid] + 1e-5f);
        d_w0[tid] = A1 * W1[tid * (F_ + 1)];
        float A2 = g2[tid] * rsqrtf(v2[tid] + 1e-5f);
        a2s[tid] = A2;  d_b2v[tid] = b2[tid] - A2 * m2[tid];
        float A3 = g3[tid] * rsqrtf(v3[tid] + 1e-5f);
        a3s[tid] = A3;  d_b3v[tid] = b3[tid] - A3 * m3[tid];
        float Ac = gc1[tid] * rsqrtf(vc1[tid] + 1e-5f);
        ac1s[tid] = Ac; d_bc1v[tid] = bc1[tid] - Ac * mc1[tid];
    }
    __syncthreads();
    // image rows k: [0,64)=hi(W), [64,128)=hi(W), [128,192)=lo(W); h = k&63
    // byte offset = k*128 + ((g>>3) ^ (k&7))*16 + (g&7)*2
    for (int i = tid; i < 192 * 64; i += 256) {
        int k = i >> 6, g = i & 63;
        int h = k & 63;
        float w2v = a2s[g] * W2[g * H_ + h];
        float w3v = a3s[g] * W3[g * H_ + h];
        __nv_bfloat16 h2 = __float2bfloat16(w2v);
        __nv_bfloat16 h3 = __float2bfloat16(w3v);
        __nv_bfloat16 v2b = (k < 128) ? h2 : __float2bfloat16(w2v - __bfloat162float(h2));
        __nv_bfloat16 v3b = (k < 128) ? h3 : __float2bfloat16(w3v - __bfloat162float(h3));
        uint32_t off = (uint32_t)k * 128u + ((((uint32_t)g >> 3) ^ ((uint32_t)k & 7u)) << 4)
                       + (((uint32_t)g & 7u) << 1);
        d_W2img[off >> 1] = __bfloat16_as_ushort(v2b);
        d_W3img[off >> 1] = __bfloat16_as_ushort(v3b);
    }
    for (int i = tid; i < H_ * H_; i += 256) {
        int k = i >> 6, g = i & 63;
        d_Wc1t[k * H_ + g] = ac1s[g] * Wc1[g * H_ + k];
    }
    for (int i = tid; i < H_ * O_; i += 256) {
        int h = i >> 7, o = i & 127;
        d_Wc2t[h * O_ + o] = Wc2[o * H_ + h];
    }
}

// ---------------- K1: A' = BN1-folded W1[:,1:] @ t ---------------------------
__global__ void ap_kernel(const float* __restrict__ t, const float* __restrict__ W1,
                          const float* __restrict__ g1, const float* __restrict__ b1,
                          const float* __restrict__ m1, const float* __restrict__ v1) {
    int bh = blockIdx.x;
    int b = bh >> 6, h = bh & 63;
    int m = threadIdx.x;
    __shared__ float w[F_];
    if (m < F_) w[m] = W1[h * (F_ + 1) + 1 + m];
    __syncthreads();
    const float* tp = t + (size_t)b * F_ * M_ + m;
    float acc = 0.f;
#pragma unroll 8
    for (int f = 0; f < F_; f++) acc = fmaf(w[f], tp[f * M_], acc);
    float A1 = g1[h] * rsqrtf(v1[h] + 1e-5f);
    float B1 = b1[h] - A1 * m1[h];
    d_Ap[bh * M_ + m] = fmaf(A1, acc, B1);
}

// ---------------- K2: column norms ------------------------------------------
__global__ void norm_kernel(const float* __restrict__ t, const float* __restrict__ s) {
    int idx = blockIdx.x * 256 + threadIdx.x;
    int b = idx / (M_ + N_);
    int r = idx - b * (M_ + N_);
    float acc = 0.f;
    if (r < M_) {
        const float* p = t + (size_t)b * F_ * M_ + r;
#pragma unroll 8
        for (int f = 0; f < F_; f++) { float v = p[f * M_]; acc = fmaf(v, v, acc); }
        d_nt[b * M_ + r] = sqrtf(acc);
    } else {
        int n = r - M_;
        const float* p = s + (size_t)b * F_ * N_ + n;
#pragma unroll 8
        for (int f = 0; f < F_; f++) { float v = p[f * N_]; acc = fmaf(v, v, acc); }
        d_ns[b * N_ + n] = sqrtf(acc);
    }
}

// ---------------- K3: cosine-similarity GEMM, stores [b][n][m] ---------------
__global__ void __launch_bounds__(256) cos_kernel(const float* __restrict__ t,
                                                  const float* __restrict__ s) {
    int b = blockIdx.z;
    int m0 = blockIdx.y * 64;
    int n0 = blockIdx.x * 64;
    __shared__ float ts[16][64];
    __shared__ float ss[16][64];
    int tid = threadIdx.x, ty = tid >> 4, tx = tid & 15;
    float acc[4][4] = {};
    const float* tb = t + (size_t)b * F_ * M_;
    const float* sb = s + (size_t)b * F_ * N_;
    for (int f0 = 0; f0 < F_; f0 += 16) {
        __syncthreads();
#pragma unroll
        for (int i = 0; i < 4; i++) {
            int e = tid + i * 256;
            int fr = e >> 6, cc = e & 63;
            ts[fr][cc] = tb[(f0 + fr) * M_ + m0 + cc];
            ss[fr][cc] = sb[(f0 + fr) * N_ + n0 + cc];
        }
        __syncthreads();
#pragma unroll
        for (int k = 0; k < 16; k++) {
            float4 av = *(const float4*)&ts[k][4 * ty];
            float4 bv = *(const float4*)&ss[k][4 * tx];
            float a0 = av.x, a1 = av.y, a2 = av.z, a3 = av.w;
            float b0 = bv.x, b1 = bv.y, b2 = bv.z, b3 = bv.w;
            acc[0][0] = fmaf(a0, b0, acc[0][0]); acc[0][1] = fmaf(a0, b1, acc[0][1]);
            acc[0][2] = fmaf(a0, b2, acc[0][2]); acc[0][3] = fmaf(a0, b3, acc[0][3]);
            acc[1][0] = fmaf(a1, b0, acc[1][0]); acc[1][1] = fmaf(a1, b1, acc[1][1]);
            acc[1][2] = fmaf(a1, b2, acc[1][2]); acc[1][3] = fmaf(a1, b3, acc[1][3]);
            acc[2][0] = fmaf(a2, b0, acc[2][0]); acc[2][1] = fmaf(a2, b1, acc[2][1]);
            acc[2][2] = fmaf(a2, b2, acc[2][2]); acc[2][3] = fmaf(a2, b3, acc[2][3]);
            acc[3][0] = fmaf(a3, b0, acc[3][0]); acc[3][1] = fmaf(a3, b1, acc[3][1]);
            acc[3][2] = fmaf(a3, b2, acc[3][2]); acc[3][3] = fmaf(a3, b3, acc[3][3]);
        }
    }
    float ntv[4], nsv[4];
#pragma unroll
    for (int r = 0; r < 4; r++) ntv[r] = d_nt[b * M_ + m0 + 4 * ty + r];
#pragma unroll
    for (int c = 0; c < 4; c++) nsv[c] = d_ns[b * N_ + n0 + 4 * tx + c];
#pragma unroll
    for (int c = 0; c < 4; c++) {
        int n = n0 + 4 * tx + c;
        float4 v;
        v.x = acc[0][c] / fmaxf(ntv[0] * nsv[c], 1e-8f);
        v.y = acc[1][c] / fmaxf(ntv[1] * nsv[c], 1e-8f);
        v.z = acc[2][c] / fmaxf(ntv[2] * nsv[c], 1e-8f);
        v.w = acc[3][c] / fmaxf(ntv[3] * nsv[c], 1e-8f);
        *(float4*)&d_cos[((size_t)b * N_ + n) * M_ + m0 + 4 * ty] = v;
    }
}

// ---------------- K4: fused MLP via mma.sync HMMA + maxpool ------------------
// SMEM map (bytes):
//  0       W2 image (24576)
//  24576   W3 image (24576)
//  49152   Xs [128 m][400B] split activations (51200)
//  100352  Ap tile [64 h][128 m] f32 (32768)
//  133120  cos [4 nl][256 m] f32 (4096)
//  137216  pn [4][64] f32 (1024)
//  138240  red [4 mb][64 g] f32 (1024)
//  139264  w0s (256) | 139520 b2s (256) | 139776 b3s (256)
#define XS_OFF   49152
#define AP_OFF   100352
#define COS_OFF  133120
#define PN_OFF   137216
#define RED_OFF  138240
#define W0_OFF   139264
#define B2_OFF   139520
#define B3_OFF   139776
#define MAIN_SMEM_BYTES 140032

__device__ __forceinline__ void do_gemm(uint32_t xs_u32, uint32_t w_u32,
                                        int lane, int gb, int mb, float acc[2][4][4]) {
    uint32_t aaddr0 = xs_u32 + (uint32_t)((mb * 32 + (lane & 15)) * ROWB + ((lane >> 4) << 4));
    uint32_t aaddr1 = aaddr0 + 16 * ROWB;
    int kk = (lane & 7) + ((lane >> 3) & 1) * 8;
    int nc0 = gb * 4 + (lane >> 4);           // 16B-chunk index of n-base (j=0)
    uint32_t baddr0 = w_u32 + (uint32_t)(kk * 128 + ((nc0 ^ (lane & 7)) << 4));
    uint32_t baddr1 = w_u32 + (uint32_t)(kk * 128 + (((nc0 + 2) ^ (lane & 7)) << 4));
#pragma unroll
    for (int k = 0; k < 12; k++) {
        uint32_t a0[4], a1[4], b0[4], b1[4];
        ldsm_x4 (a0, aaddr0 + k * 32);
        ldsm_x4 (a1, aaddr1 + k * 32);
        ldsm_x4t(b0, baddr0 + k * 2048);
        ldsm_x4t(b1, baddr1 + k * 2048);
        mma16816(acc[0][0], a0, b0[0], b0[1]); mma16816(acc[0][1], a0, b0[2], b0[3]);
        mma16816(acc[0][2], a0, b1[0], b1[1]); mma16816(acc[0][3], a0, b1[2], b1[3]);
        mma16816(acc[1][0], a1, b0[0], b0[1]); mma16816(acc[1][1], a1, b0[2], b0[3]);
        mma16816(acc[1][2], a1, b1[0], b1[1]); mma16816(acc[1][3], a1, b1[2], b1[3]);
    }
}

__global__ void __launch_bounds__(256) main_kernel() {
    extern __shared__ char smem[];
    float* aps  = (float*)(smem + AP_OFF);
    float* coss = (float*)(smem + COS_OFF);
    float* pn   = (float*)(smem + PN_OFF);
    float* red  = (float*)(smem + RED_OFF);
    float* w0s  = (float*)(smem + W0_OFF);
    float* b2s  = (float*)(smem + B2_OFF);
    float* b3s  = (float*)(smem + B3_OFF);

    uint32_t sb32 = smem_to_u32(smem);
    uint32_t xs_u32 = sb32 + XS_OFF;

    int tid = threadIdx.x;
    int wid = tid >> 5, lane = tid & 31;
    int gb = wid >> 2, mb = wid & 3;
    int b = blockIdx.y;
    int n0 = blockIdx.x * NPB;

    // stage weights + cos + biases
    {
        const uint4* sw = (const uint4*)d_W2img;   // W2 then W3 contiguous? no — two arrays
        uint4* dw = (uint4*)smem;
#pragma unroll
        for (int i = 0; i < 6; i++) dw[tid + i * 256] = sw[tid + i * 256];
        const uint4* sw3 = (const uint4*)d_W3img;
        uint4* dw3 = (uint4*)(smem + 24576);
#pragma unroll
        for (int i = 0; i < 6; i++) dw3[tid + i * 256] = sw3[tid + i * 256];
        const float4* cg = (const float4*)(d_cos + ((size_t)b * N_ + n0) * M_);
        ((float4*)coss)[tid] = cg[tid];
        if (tid < 64) {
            w0s[tid] = d_w0[tid];
            b2s[tid] = d_b2v[tid];
            b3s[tid] = d_b3v[tid];
        }
        pn[tid] = 0.f;
    }

    for (int mt = 0; mt < 2; mt++) {
        __syncthreads();   // protect aps reuse + initial stage
        {
            const float4* ag = (const float4*)d_Ap;
            float4* as = (float4*)aps;
#pragma unroll
            for (int i = 0; i < 8; i++) {
                int e = tid + i * 256;
                int h = e >> 5, q = e & 31;
                as[e] = ag[((size_t)b * 64 + h) * 64 + mt * 32 + q];
            }
        }
        __syncthreads();

        for (int nl = 0; nl < NPB; nl++) {
            // ---- layer 1: build split X1 in Xs ----
            {
                int m = tid & 127;
                int hb = (tid >> 7) * 32;
                float cv = coss[nl * 256 + mt * 128 + m];
                char* row = smem + XS_OFF + m * ROWB;
#pragma unroll
                for (int c = 0; c < 16; c++) {
                    int h0 = hb + 2 * c;
                    float y0 = fmaxf(fmaf(w0s[h0],     cv, aps[h0 * 128 + m]), 0.f);
                    float y1 = fmaxf(fmaf(w0s[h0 + 1], cv, aps[(h0 + 1) * 128 + m]), 0.f);
                    uint32_t lo, hi = pack_split(y0, y1, lo);
                    *(uint32_t*)(row + h0 * 2)       = hi;
                    *(uint32_t*)(row + 128 + h0 * 2) = lo;
                    *(uint32_t*)(row + 256 + h0 * 2) = hi;
                }
            }
            __syncthreads();

            // ---- GEMM1 ----
            float acc[2][4][4] = {};
            do_gemm(xs_u32, sb32, lane, gb, mb, acc);
            __syncthreads();   // all reads of Xs done before overwrite

            // ---- epilogue 1: relu(+b2), split, write back to Xs ----
            {
                int g0 = gb * 32 + 2 * (lane & 3);
                int r0 = mb * 32 + (lane >> 2);
#pragma unroll
                for (int i = 0; i < 2; i++) {
#pragma unroll
                    for (int t = 0; t < 4; t++) {
                        int gg = g0 + t * 8;
                        float bb0 = b2s[gg], bb1 = b2s[gg + 1];
                        // row r0 + i*16
                        {
                            float y0 = fmaxf(acc[i][t][0] + bb0, 0.f);
                            float y1 = fmaxf(acc[i][t][1] + bb1, 0.f);
                            uint32_t lo, hi = pack_split(y0, y1, lo);
                            char* row = smem + XS_OFF + (r0 + i * 16) * ROWB;
                            *(uint32_t*)(row + gg * 2)       = hi;
                            *(uint32_t*)(row + 128 + gg * 2) = lo;
                            *(uint32_t*)(row + 256 + gg * 2) = hi;
                        }
                        // row r0 + i*16 + 8
                        {
                            float y0 = fmaxf(acc[i][t][2] + bb0, 0.f);
                            float y1 = fmaxf(acc[i][t][3] + bb1, 0.f);
                            uint32_t lo, hi = pack_split(y0, y1, lo);
                            char* row = smem + XS_OFF + (r0 + i * 16 + 8) * ROWB;
                            *(uint32_t*)(row + gg * 2)       = hi;
                            *(uint32_t*)(row + 128 + gg * 2) = lo;
                            *(uint32_t*)(row + 256 + gg * 2) = hi;
                        }
                    }
                }
            }
            __syncthreads();

            // ---- GEMM2 ----
            float acc2[2][4][4] = {};
            do_gemm(xs_u32, sb32 + 24576, lane, gb, mb, acc2);

            // ---- epilogue 2: relu(+b3), max over m ----
            {
                int g0 = gb * 32 + 2 * (lane & 3);
#pragma unroll
                for (int t = 0; t < 4; t++) {
#pragma unroll
                    for (int c = 0; c < 2; c++) {
                        int gg = g0 + t * 8 + c;
                        float v = fmaxf(fmaxf(acc2[0][t][c], acc2[0][t][2 + c]),
                                        fmaxf(acc2[1][t][c], acc2[1][t][2 + c]));
                        v = fmaxf(v + b3s[gg], 0.f);
                        v = fmaxf(v, __shfl_xor_sync(0xFFFFFFFFu, v, 4));
                        v = fmaxf(v, __shfl_xor_sync(0xFFFFFFFFu, v, 8));
                        v = fmaxf(v, __shfl_xor_sync(0xFFFFFFFFu, v, 16));
                        if (lane < 4) red[mb * 64 + gg] = v;
                    }
                }
            }
            __syncthreads();
            if (tid < 64) {
                float v = fmaxf(fmaxf(red[tid], red[64 + tid]),
                                fmaxf(red[128 + tid], red[192 + tid]));
                pn[nl * 64 + tid] = fmaxf(pn[nl * 64 + tid], v);
            }
            __syncthreads();
        }
    }

    // write pooled features
    {
        int nl = tid >> 6, h = tid & 63;
        d_p[((size_t)b * N_ + n0 + nl) * H_ + h] = pn[tid];
    }
}

// ---------------- K5: head (Wc1 -> relu -> Wc2 + bc2) ------------------------
#define HEAD_SMEM_FLOATS 20608
__global__ void __launch_bounds__(256) head_kernel(const float* __restrict__ bc2,
                                                   float* __restrict__ out) {
    extern __shared__ float smf[];
    float* wc1s = smf;
    float* wc2s = smf + 4096;
    float* ps   = smf + 12288;
    float* cs   = smf + 16384;
    float* bc1s = smf + 20544;

    int b = blockIdx.y, n0 = blockIdx.x * 64;
    int tid = threadIdx.x;
#pragma unroll
    for (int i = 0; i < 16; i++) {
        int idx = tid + i * 256;
        wc1s[idx] = d_Wc1t[idx];
        ps[idx]   = d_p[((size_t)b * N_ + n0) * H_ + idx];
    }
#pragma unroll
    for (int i = 0; i < 32; i++) {
        int idx = tid + i * 256;
        wc2s[idx] = d_Wc2t[idx];
    }
    if (tid < 64) bc1s[tid] = d_bc1v[tid];
    __syncthreads();

#pragma unroll
    for (int i = 0; i < 16; i++) {
        int idx = tid + i * 256;
        int nn = idx >> 6, g = idx & 63;
        float acc = bc1s[g];
#pragma unroll 16
        for (int h = 0; h < 64; h++) acc = fmaf(wc1s[h * 64 + g], ps[nn * 64 + h], acc);
        cs[nn * 65 + g] = fmaxf(acc, 0.f);
    }
    __syncthreads();

#pragma unroll
    for (int i = 0; i < 32; i++) {
        int idx = tid + i * 256;
        int o = idx >> 6, nn = idx & 63;
        float acc = __ldg(bc2 + o);
#pragma unroll 16
        for (int h = 0; h < 64; h++) acc = fmaf(wc2s[h * 128 + o], cs[nn * 65 + h], acc);
        out[((size_t)b * O_ + o) * N_ + n0 + nn] = acc;
    }
}

// ---------------- launch ------------------------------------------------------
extern "C" void kernel_launch(void* const* d_in, const int* in_sizes, int n_in,
                              void* d_out, int out_size) {
    const float* t   = (const float*)d_in[0];
    const float* s   = (const float*)d_in[1];
    const float* W1  = (const float*)d_in[2];
    const float* W2  = (const float*)d_in[3];
    const float* W3  = (const float*)d_in[4];
    const float* Wc1 = (const float*)d_in[5];
    const float* Wc2 = (const float*)d_in[6];
    const float* bc2 = (const float*)d_in[7];
    const float* g1 = (const float*)d_in[8],  *b1 = (const float*)d_in[9];
    const float* m1 = (const float*)d_in[10], *v1 = (const float*)d_in[11];
    const float* g2 = (const float*)d_in[12], *b2 = (const float*)d_in[13];
    const float* m2 = (const float*)d_in[14], *v2 = (const float*)d_in[15];
    const float* g3 = (const float*)d_in[16], *b3 = (const float*)d_in[17];
    const float* m3 = (const float*)d_in[18], *v3 = (const float*)d_in[19];
    const float* gc1 = (const float*)d_in[20], *bc1 = (const float*)d_in[21];
    const float* mc1 = (const float*)d_in[22], *vc1 = (const float*)d_in[23];
    float* out = (float*)d_out;

    cudaFuncSetAttribute(main_kernel, cudaFuncAttributeMaxDynamicSharedMemorySize,
                         MAIN_SMEM_BYTES);
    cudaFuncSetAttribute(head_kernel, cudaFuncAttributeMaxDynamicSharedMemorySize,
                         HEAD_SMEM_FLOATS * 4);

    fold_kernel<<<1, 256>>>(W1, W2, W3, Wc1, Wc2, g1, v1,
                            g2, b2, m2, v2, g3, b3, m3, v3, gc1, bc1, mc1, vc1);
    ap_kernel<<<B_ * H_, 256>>>(t, W1, g1, b1, m1, v1);
    norm_kernel<<<(B_ * (M_ + N_)) / 256, 256>>>(t, s);
    cos_kernel<<<dim3(N_ / 64, M_ / 64, B_), 256>>>(t, s);
    main_kernel<<<dim3(N_ / NPB, B_), 256, MAIN_SMEM_BYTES>>>();
    head_kernel<<<dim3(N_ / 64, B_), 256, HEAD_SMEM_FLOATS * 4>>>(bc2, out);
}

// round 4
// speedup vs baseline: 2.7790x; 1.3492x over previous
#include <cuda_runtime.h>
#include <cuda_bf16.h>
#include <cstdint>

#define B_ 8
#define F_ 128
#define M_ 256
#define N_ 1024
#define H_ 64
#define O_ 128
#define NPB 4
#define ROWB 272   // Xs bytes per m-row: 256 B (hi|lo) + 16 B pad (17 x 16B chunks)

// ---------------- scratch (device globals; no allocations allowed) ----------
__device__ __align__(16) float d_cos[B_ * N_ * M_];   // [b][n][m]
__device__ __align__(16) float d_Ap [B_ * H_ * M_];   // [b][h][m]
__device__ float d_nt [B_ * M_];
__device__ float d_ns [B_ * N_];
__device__ float d_w0 [H_];
__device__ float d_b2v[H_], d_b3v[H_], d_bc1v[H_];
// ldmatrix-ready bf16 weight images: [k=128 rows][64 g]; rows 0-63 = hi(W), 64-127 = lo(W)
// 128B rows, 16B-chunk XOR swizzle
__device__ __align__(16) unsigned short d_W2img[128 * 64];
__device__ __align__(16) unsigned short d_W3img[128 * 64];
__device__ __align__(16) float d_Wc1t[H_ * H_];
__device__ __align__(16) float d_Wc2t[H_ * O_];
__device__ __align__(16) float d_p  [B_ * N_ * H_];

// ================= tensor-core helpers (sm_80-era PTX, valid on sm_103) =====
__device__ __forceinline__ uint32_t smem_to_u32(const void* p) {
    uint32_t a;
    asm("{ .reg .u64 t; cvta.to.shared.u64 t, %1; cvt.u32.u64 %0, t; }" : "=r"(a) : "l"(p));
    return a;
}
__device__ __forceinline__ void ldsm_x4(uint32_t r[4], uint32_t addr) {
    asm volatile("ldmatrix.sync.aligned.m8n8.x4.shared.b16 {%0,%1,%2,%3}, [%4];"
                 : "=r"(r[0]), "=r"(r[1]), "=r"(r[2]), "=r"(r[3]) : "r"(addr));
}
__device__ __forceinline__ void ldsm_x4t(uint32_t r[4], uint32_t addr) {
    asm volatile("ldmatrix.sync.aligned.m8n8.x4.trans.shared.b16 {%0,%1,%2,%3}, [%4];"
                 : "=r"(r[0]), "=r"(r[1]), "=r"(r[2]), "=r"(r[3]) : "r"(addr));
}
__device__ __forceinline__ void mma16816(float d[4], const uint32_t a[4],
                                         uint32_t b0, uint32_t b1) {
    asm volatile("mma.sync.aligned.m16n8k16.row.col.f32.bf16.bf16.f32 "
                 "{%0,%1,%2,%3}, {%4,%5,%6,%7}, {%8,%9}, {%0,%1,%2,%3};"
                 : "+f"(d[0]), "+f"(d[1]), "+f"(d[2]), "+f"(d[3])
                 : "r"(a[0]), "r"(a[1]), "r"(a[2]), "r"(a[3]), "r"(b0), "r"(b1));
}
// fast 2-value hi/lo bf16 split: hi = bf16x2(y1,y0); lo = bf16x2(y1-hi1, y0-hi0)
__device__ __forceinline__ uint32_t pack_split(float y0, float y1, uint32_t& lo) {
    uint32_t hi;
    asm("cvt.rn.bf16x2.f32 %0, %1, %2;" : "=r"(hi) : "f"(y1), "f"(y0));
    float y0h = __uint_as_float(hi << 16);
    float y1h = __uint_as_float(hi & 0xFFFF0000u);
    asm("cvt.rn.bf16x2.f32 %0, %1, %2;" : "=r"(lo) : "f"(y1 - y1h), "f"(y0 - y0h));
    return hi;
}

// ---------------- K0: fold BN into weights, emit ldmatrix bf16 images --------
__global__ void fold_kernel(const float* __restrict__ W1, const float* __restrict__ W2,
                            const float* __restrict__ W3, const float* __restrict__ Wc1,
                            const float* __restrict__ Wc2,
                            const float* __restrict__ g1, const float* __restrict__ v1,
                            const float* __restrict__ g2, const float* __restrict__ b2,
                            const float* __restrict__ m2, const float* __restrict__ v2,
                            const float* __restrict__ g3, const float* __restrict__ b3,
                            const float* __restrict__ m3, const float* __restrict__ v3,
                            const float* __restrict__ gc1, const float* __restrict__ bc1,
                            const float* __restrict__ mc1, const float* __restrict__ vc1) {
    __shared__ float a2s[H_], a3s[H_], ac1s[H_];
    int tid = threadIdx.x;
    if (tid < H_) {
        float A1 = g1[tid] * rsqrtf(v1[tid] + 1e-5f);
        d_w0[tid] = A1 * W1[tid * (F_ + 1)];
        float A2 = g2[tid] * rsqrtf(v2[tid] + 1e-5f);
        a2s[tid] = A2;  d_b2v[tid] = b2[tid] - A2 * m2[tid];
        float A3 = g3[tid] * rsqrtf(v3[tid] + 1e-5f);
        a3s[tid] = A3;  d_b3v[tid] = b3[tid] - A3 * m3[tid];
        float Ac = gc1[tid] * rsqrtf(vc1[tid] + 1e-5f);
        ac1s[tid] = Ac; d_bc1v[tid] = bc1[tid] - Ac * mc1[tid];
    }
    __syncthreads();
    // image rows k: [0,64)=hi(W), [64,128)=lo(W); h = k&63
    // byte offset = k*128 + ((g>>3) ^ (k&7))*16 + (g&7)*2
    for (int i = tid; i < 128 * 64; i += 256) {
        int k = i >> 6, g = i & 63;
        int h = k & 63;
        float w2v = a2s[g] * W2[g * H_ + h];
        float w3v = a3s[g] * W3[g * H_ + h];
        __nv_bfloat16 h2 = __float2bfloat16(w2v);
        __nv_bfloat16 h3 = __float2bfloat16(w3v);
        __nv_bfloat16 v2b = (k < 64) ? h2 : __float2bfloat16(w2v - __bfloat162float(h2));
        __nv_bfloat16 v3b = (k < 64) ? h3 : __float2bfloat16(w3v - __bfloat162float(h3));
        uint32_t off = (uint32_t)k * 128u + ((((uint32_t)g >> 3) ^ ((uint32_t)k & 7u)) << 4)
                       + (((uint32_t)g & 7u) << 1);
        d_W2img[off >> 1] = __bfloat16_as_ushort(v2b);
        d_W3img[off >> 1] = __bfloat16_as_ushort(v3b);
    }
    for (int i = tid; i < H_ * H_; i += 256) {
        int k = i >> 6, g = i & 63;
        d_Wc1t[k * H_ + g] = ac1s[g] * Wc1[g * H_ + k];
    }
    for (int i = tid; i < H_ * O_; i += 256) {
        int h = i >> 7, o = i & 127;
        d_Wc2t[h * O_ + o] = Wc2[o * H_ + h];
    }
}

// ---------------- K1: A' = BN1-folded W1[:,1:] @ t ---------------------------
__global__ void ap_kernel(const float* __restrict__ t, const float* __restrict__ W1,
                          const float* __restrict__ g1, const float* __restrict__ b1,
                          const float* __restrict__ m1, const float* __restrict__ v1) {
    int bh = blockIdx.x;
    int b = bh >> 6, h = bh & 63;
    int m = threadIdx.x;
    __shared__ float w[F_];
    if (m < F_) w[m] = W1[h * (F_ + 1) + 1 + m];
    __syncthreads();
    const float* tp = t + (size_t)b * F_ * M_ + m;
    float acc = 0.f;
#pragma unroll 8
    for (int f = 0; f < F_; f++) acc = fmaf(w[f], tp[f * M_], acc);
    float A1 = g1[h] * rsqrtf(v1[h] + 1e-5f);
    float B1 = b1[h] - A1 * m1[h];
    d_Ap[bh * M_ + m] = fmaf(A1, acc, B1);
}

// ---------------- K2: column norms ------------------------------------------
__global__ void norm_kernel(const float* __restrict__ t, const float* __restrict__ s) {
    int idx = blockIdx.x * 256 + threadIdx.x;
    int b = idx / (M_ + N_);
    int r = idx - b * (M_ + N_);
    float acc = 0.f;
    if (r < M_) {
        const float* p = t + (size_t)b * F_ * M_ + r;
#pragma unroll 8
        for (int f = 0; f < F_; f++) { float v = p[f * M_]; acc = fmaf(v, v, acc); }
        d_nt[b * M_ + r] = sqrtf(acc);
    } else {
        int n = r - M_;
        const float* p = s + (size_t)b * F_ * N_ + n;
#pragma unroll 8
        for (int f = 0; f < F_; f++) { float v = p[f * N_]; acc = fmaf(v, v, acc); }
        d_ns[b * N_ + n] = sqrtf(acc);
    }
}

// ---------------- K3: cosine-similarity GEMM, stores [b][n][m] ---------------
__global__ void __launch_bounds__(256) cos_kernel(const float* __restrict__ t,
                                                  const float* __restrict__ s) {
    int b = blockIdx.z;
    int m0 = blockIdx.y * 64;
    int n0 = blockIdx.x * 64;
    __shared__ float ts[16][64];
    __shared__ float ss[16][64];
    int tid = threadIdx.x, ty = tid >> 4, tx = tid & 15;
    float acc[4][4] = {};
    const float* tb = t + (size_t)b * F_ * M_;
    const float* sb = s + (size_t)b * F_ * N_;
    for (int f0 = 0; f0 < F_; f0 += 16) {
        __syncthreads();
#pragma unroll
        for (int i = 0; i < 4; i++) {
            int e = tid + i * 256;
            int fr = e >> 6, cc = e & 63;
            ts[fr][cc] = tb[(f0 + fr) * M_ + m0 + cc];
            ss[fr][cc] = sb[(f0 + fr) * N_ + n0 + cc];
        }
        __syncthreads();
#pragma unroll
        for (int k = 0; k < 16; k++) {
            float4 av = *(const float4*)&ts[k][4 * ty];
            float4 bv = *(const float4*)&ss[k][4 * tx];
            float a0 = av.x, a1 = av.y, a2 = av.z, a3 = av.w;
            float b0 = bv.x, b1 = bv.y, b2 = bv.z, b3 = bv.w;
            acc[0][0] = fmaf(a0, b0, acc[0][0]); acc[0][1] = fmaf(a0, b1, acc[0][1]);
            acc[0][2] = fmaf(a0, b2, acc[0][2]); acc[0][3] = fmaf(a0, b3, acc[0][3]);
            acc[1][0] = fmaf(a1, b0, acc[1][0]); acc[1][1] = fmaf(a1, b1, acc[1][1]);
            acc[1][2] = fmaf(a1, b2, acc[1][2]); acc[1][3] = fmaf(a1, b3, acc[1][3]);
            acc[2][0] = fmaf(a2, b0, acc[2][0]); acc[2][1] = fmaf(a2, b1, acc[2][1]);
            acc[2][2] = fmaf(a2, b2, acc[2][2]); acc[2][3] = fmaf(a2, b3, acc[2][3]);
            acc[3][0] = fmaf(a3, b0, acc[3][0]); acc[3][1] = fmaf(a3, b1, acc[3][1]);
            acc[3][2] = fmaf(a3, b2, acc[3][2]); acc[3][3] = fmaf(a3, b3, acc[3][3]);
        }
    }
    float ntv[4], nsv[4];
#pragma unroll
    for (int r = 0; r < 4; r++) ntv[r] = d_nt[b * M_ + m0 + 4 * ty + r];
#pragma unroll
    for (int c = 0; c < 4; c++) nsv[c] = d_ns[b * N_ + n0 + 4 * tx + c];
#pragma unroll
    for (int c = 0; c < 4; c++) {
        int n = n0 + 4 * tx + c;
        float4 v;
        v.x = acc[0][c] / fmaxf(ntv[0] * nsv[c], 1e-8f);
        v.y = acc[1][c] / fmaxf(ntv[1] * nsv[c], 1e-8f);
        v.z = acc[2][c] / fmaxf(ntv[2] * nsv[c], 1e-8f);
        v.w = acc[3][c] / fmaxf(ntv[3] * nsv[c], 1e-8f);
        *(float4*)&d_cos[((size_t)b * N_ + n) * M_ + m0 + 4 * ty] = v;
    }
}

// ---------------- K4: fused MLP via mma.sync HMMA + maxpool ------------------
// SMEM map (bytes):
//  0       W2 image (16384)
//  16384   W3 image (16384)
//  32768   Xs [128 m][272B] split activations (34816)
//  67584   Ap tile [64 h][128 m] f32 (32768)
//  100352  cos [4 nl][256 m] f32 (4096)
//  104448  red [4 nl][4 mb][64 g] f32 (4096)
//  108544  w0s (256) | 108800 b2s (256) | 109056 b3s (256)
#define XS_OFF   32768
#define AP_OFF   67584
#define COS_OFF  100352
#define RED_OFF  104448
#define W0_OFF   108544
#define B2_OFF   108800
#define B3_OFF   109056
#define MAIN_SMEM_BYTES 109312

__device__ __forceinline__ void do_gemm(uint32_t xs_u32, uint32_t w_u32,
                                        int lane, int gb, int mb, float acc[2][4][4]) {
    uint32_t aaddr0 = xs_u32 + (uint32_t)((mb * 32 + (lane & 15)) * ROWB + ((lane >> 4) << 4));
    uint32_t aaddr1 = aaddr0 + 16 * ROWB;
    int kk = (lane & 7) + ((lane >> 3) & 1) * 8;
    int nc0 = gb * 4 + (lane >> 4);
    uint32_t baddr0 = w_u32 + (uint32_t)(kk * 128 + ((nc0 ^ (lane & 7)) << 4));
    uint32_t baddr1 = w_u32 + (uint32_t)(kk * 128 + (((nc0 + 2) ^ (lane & 7)) << 4));
    // K=192 in 12 k16-steps; A segs: hi, lo, hi(reuse); B segs: hi, hi(reuse), lo
#pragma unroll
    for (int k = 0; k < 12; k++) {
        int aoff = (k < 8 ? k : k - 8) * 32;
        int boff = (k < 4 ? k : k - 4) * 2048;
        uint32_t a0[4], a1[4], b0[4], b1[4];
        ldsm_x4 (a0, aaddr0 + aoff);
        ldsm_x4 (a1, aaddr1 + aoff);
        ldsm_x4t(b0, baddr0 + boff);
        ldsm_x4t(b1, baddr1 + boff);
        mma16816(acc[0][0], a0, b0[0], b0[1]); mma16816(acc[0][1], a0, b0[2], b0[3]);
        mma16816(acc[0][2], a0, b1[0], b1[1]); mma16816(acc[0][3], a0, b1[2], b1[3]);
        mma16816(acc[1][0], a1, b0[0], b0[1]); mma16816(acc[1][1], a1, b0[2], b0[3]);
        mma16816(acc[1][2], a1, b1[0], b1[1]); mma16816(acc[1][3], a1, b1[2], b1[3]);
    }
}

__global__ void __launch_bounds__(256, 2) main_kernel() {
    extern __shared__ char smem[];
    float* aps  = (float*)(smem + AP_OFF);
    float* coss = (float*)(smem + COS_OFF);
    float* red  = (float*)(smem + RED_OFF);
    float* w0s  = (float*)(smem + W0_OFF);
    float* b2s  = (float*)(smem + B2_OFF);
    float* b3s  = (float*)(smem + B3_OFF);

    uint32_t sb32 = smem_to_u32(smem);
    uint32_t xs_u32 = sb32 + XS_OFF;

    int tid = threadIdx.x;
    int wid = tid >> 5, lane = tid & 31;
    int gb = wid >> 2, mb = wid & 3;
    int b = blockIdx.y;
    int n0 = blockIdx.x * NPB;

    // stage weights + cos + biases; init red
    {
        const uint4* sw2 = (const uint4*)d_W2img;
        const uint4* sw3 = (const uint4*)d_W3img;
        uint4* dw2 = (uint4*)smem;
        uint4* dw3 = (uint4*)(smem + 16384);
#pragma unroll
        for (int i = 0; i < 4; i++) {
            dw2[tid + i * 256] = sw2[tid + i * 256];
            dw3[tid + i * 256] = sw3[tid + i * 256];
        }
        const float4* cg = (const float4*)(d_cos + ((size_t)b * N_ + n0) * M_);
        ((float4*)coss)[tid] = cg[tid];
        if (tid < 64) {
            w0s[tid] = d_w0[tid];
            b2s[tid] = d_b2v[tid];
            b3s[tid] = d_b3v[tid];
        }
#pragma unroll
        for (int i = 0; i < 4; i++) red[tid + i * 256] = 0.f;
    }

    for (int mt = 0; mt < 2; mt++) {
        __syncthreads();   // staging / prev-iter Xs+aps readers done
        {
            const float4* ag = (const float4*)d_Ap;
            float4* as = (float4*)aps;
#pragma unroll
            for (int i = 0; i < 8; i++) {
                int e = tid + i * 256;
                int h = e >> 5, q = e & 31;
                as[e] = ag[((size_t)b * 64 + h) * 64 + mt * 32 + q];
            }
        }
        __syncthreads();

        for (int nl = 0; nl < NPB; nl++) {
            // ---- layer 1: build split X1 in Xs ----
            {
                int m = tid & 127;
                int hb = (tid >> 7) * 32;
                float cv = coss[nl * 256 + mt * 128 + m];
                char* row = smem + XS_OFF + m * ROWB;
#pragma unroll
                for (int c = 0; c < 16; c++) {
                    int h0 = hb + 2 * c;
                    float y0 = fmaxf(fmaf(w0s[h0],     cv, aps[h0 * 128 + m]), 0.f);
                    float y1 = fmaxf(fmaf(w0s[h0 + 1], cv, aps[(h0 + 1) * 128 + m]), 0.f);
                    uint32_t lo, hi = pack_split(y0, y1, lo);
                    *(uint32_t*)(row + h0 * 2)       = hi;
                    *(uint32_t*)(row + 128 + h0 * 2) = lo;
                }
            }
            __syncthreads();

            // ---- GEMM1 ----
            float acc[2][4][4] = {};
            do_gemm(xs_u32, sb32, lane, gb, mb, acc);
            __syncthreads();   // all reads of Xs done before overwrite

            // ---- epilogue 1: relu(+b2), split, write back to Xs ----
            {
                int g0 = gb * 32 + 2 * (lane & 3);
                int r0 = mb * 32 + (lane >> 2);
#pragma unroll
                for (int i = 0; i < 2; i++) {
#pragma unroll
                    for (int t = 0; t < 4; t++) {
                        int gg = g0 + t * 8;
                        float bb0 = b2s[gg], bb1 = b2s[gg + 1];
                        {
                            float y0 = fmaxf(acc[i][t][0] + bb0, 0.f);
                            float y1 = fmaxf(acc[i][t][1] + bb1, 0.f);
                            uint32_t lo, hi = pack_split(y0, y1, lo);
                            char* row = smem + XS_OFF + (r0 + i * 16) * ROWB;
                            *(uint32_t*)(row + gg * 2)       = hi;
                            *(uint32_t*)(row + 128 + gg * 2) = lo;
                        }
                        {
                            float y0 = fmaxf(acc[i][t][2] + bb0, 0.f);
                            float y1 = fmaxf(acc[i][t][3] + bb1, 0.f);
                            uint32_t lo, hi = pack_split(y0, y1, lo);
                            char* row = smem + XS_OFF + (r0 + i * 16 + 8) * ROWB;
                            *(uint32_t*)(row + gg * 2)       = hi;
                            *(uint32_t*)(row + 128 + gg * 2) = lo;
                        }
                    }
                }
            }
            __syncthreads();

            // ---- GEMM2 ----
            float acc2[2][4][4] = {};
            do_gemm(xs_u32, sb32 + 16384, lane, gb, mb, acc2);

            // ---- epilogue 2: relu(+b3), max over m -> red (race-free RMW) ----
            {
                int g0 = gb * 32 + 2 * (lane & 3);
#pragma unroll
                for (int t = 0; t < 4; t++) {
#pragma unroll
                    for (int c = 0; c < 2; c++) {
                        int gg = g0 + t * 8 + c;
                        float v = fmaxf(fmaxf(acc2[0][t][c], acc2[0][t][2 + c]),
                                        fmaxf(acc2[1][t][c], acc2[1][t][2 + c]));
                        v = fmaxf(v + b3s[gg], 0.f);
                        v = fmaxf(v, __shfl_xor_sync(0xFFFFFFFFu, v, 4));
                        v = fmaxf(v, __shfl_xor_sync(0xFFFFFFFFu, v, 8));
                        v = fmaxf(v, __shfl_xor_sync(0xFFFFFFFFu, v, 16));
                        if (lane < 4) {
                            int ri = nl * 256 + mb * 64 + gg;
                            red[ri] = fmaxf(red[ri], v);
                        }
                    }
                }
            }
            __syncthreads();  // Xs reads (GEMM2) done before next build overwrites
        }
    }

    // final pooled reduce + write
    {
        int nl = tid >> 6, h = tid & 63;
        const float* r = red + nl * 256;
        float v = fmaxf(fmaxf(r[h], r[64 + h]), fmaxf(r[128 + h], r[192 + h]));
        d_p[((size_t)b * N_ + n0 + nl) * H_ + h] = v;
    }
}

// ---------------- K5: head (Wc1 -> relu -> Wc2 + bc2) ------------------------
#define HEAD_SMEM_FLOATS 20608
__global__ void __launch_bounds__(256) head_kernel(const float* __restrict__ bc2,
                                                   float* __restrict__ out) {
    extern __shared__ float smf[];
    float* wc1s = smf;
    float* wc2s = smf + 4096;
    float* ps   = smf + 12288;
    float* cs   = smf + 16384;
    float* bc1s = smf + 20544;

    int b = blockIdx.y, n0 = blockIdx.x * 64;
    int tid = threadIdx.x;
#pragma unroll
    for (int i = 0; i < 16; i++) {
        int idx = tid + i * 256;
        wc1s[idx] = d_Wc1t[idx];
        ps[idx]   = d_p[((size_t)b * N_ + n0) * H_ + idx];
    }
#pragma unroll
    for (int i = 0; i < 32; i++) {
        int idx = tid + i * 256;
        wc2s[idx] = d_Wc2t[idx];
    }
    if (tid < 64) bc1s[tid] = d_bc1v[tid];
    __syncthreads();

#pragma unroll
    for (int i = 0; i < 16; i++) {
        int idx = tid + i * 256;
        int nn = idx >> 6, g = idx & 63;
        float acc = bc1s[g];
#pragma unroll 16
        for (int h = 0; h < 64; h++) acc = fmaf(wc1s[h * 64 + g], ps[nn * 64 + h], acc);
        cs[nn * 65 + g] = fmaxf(acc, 0.f);
    }
    __syncthreads();

#pragma unroll
    for (int i = 0; i < 32; i++) {
        int idx = tid + i * 256;
        int o = idx >> 6, nn = idx & 63;
        float acc = __ldg(bc2 + o);
#pragma unroll 16
        for (int h = 0; h < 64; h++) acc = fmaf(wc2s[h * 128 + o], cs[nn * 65 + h], acc);
        out[((size_t)b * O_ + o) * N_ + n0 + nn] = acc;
    }
}

// ---------------- launch ------------------------------------------------------
extern "C" void kernel_launch(void* const* d_in, const int* in_sizes, int n_in,
                              void* d_out, int out_size) {
    const float* t   = (const float*)d_in[0];
    const float* s   = (const float*)d_in[1];
    const float* W1  = (const float*)d_in[2];
    const float* W2  = (const float*)d_in[3];
    const float* W3  = (const float*)d_in[4];
    const float* Wc1 = (const float*)d_in[5];
    const float* Wc2 = (const float*)d_in[6];
    const float* bc2 = (const float*)d_in[7];
    const float* g1 = (const float*)d_in[8],  *b1 = (const float*)d_in[9];
    const float* m1 = (const float*)d_in[10], *v1 = (const float*)d_in[11];
    const float* g2 = (const float*)d_in[12], *b2 = (const float*)d_in[13];
    const float* m2 = (const float*)d_in[14], *v2 = (const float*)d_in[15];
    const float* g3 = (const float*)d_in[16], *b3 = (const float*)d_in[17];
    const float* m3 = (const float*)d_in[18], *v3 = (const float*)d_in[19];
    const float* gc1 = (const float*)d_in[20], *bc1 = (const float*)d_in[21];
    const float* mc1 = (const float*)d_in[22], *vc1 = (const float*)d_in[23];
    float* out = (float*)d_out;

    cudaFuncSetAttribute(main_kernel, cudaFuncAttributeMaxDynamicSharedMemorySize,
                         MAIN_SMEM_BYTES);
    cudaFuncSetAttribute(head_kernel, cudaFuncAttributeMaxDynamicSharedMemorySize,
                         HEAD_SMEM_FLOATS * 4);

    fold_kernel<<<1, 256>>>(W1, W2, W3, Wc1, Wc2, g1, v1,
                            g2, b2, m2, v2, g3, b3, m3, v3, gc1, bc1, mc1, vc1);
    ap_kernel<<<B_ * H_, 256>>>(t, W1, g1, b1, m1, v1);
    norm_kernel<<<(B_ * (M_ + N_)) / 256, 256>>>(t, s);
    cos_kernel<<<dim3(N_ / 64, M_ / 64, B_), 256>>>(t, s);
    main_kernel<<<dim3(N_ / NPB, B_), 256, MAIN_SMEM_BYTES>>>();
    head_kernel<<<dim3(N_ / 64, B_), 256, HEAD_SMEM_FLOATS * 4>>>(bc2, out);
}